// round 3
// baseline (speedup 1.0000x reference)
#include <cuda_runtime.h>

#define BATCH 16

// ---------------- scratch (no allocations allowed) ----------------
__device__ float g_bufA[BATCH * 64 * 1024];
__device__ float g_bufB[BATCH * 64 * 1024];
__device__ float g_e2[512];

// =====================================================================
// conv1: x(16,768,4096) -> (16,32,2048), k4 s2 p1, bias, ReLU
// grid (16,16) block 256.  tile 32o x 128t, c-chunks of 16.
// =====================================================================
__global__ void __launch_bounds__(256) k_conv1(
    const float* __restrict__ x, const float* __restrict__ w,
    const float* __restrict__ bias, float* __restrict__ out) {
  __shared__ float xs[16 * 260];   // [16][260], 258 valid
  __shared__ float ws[64 * 32];    // [(c*4+k)][o]
  const int b   = blockIdx.y;
  const int T0  = blockIdx.x * 128;
  const int tid = threadIdx.x;
  const int og  = tid & 7;    // 8 groups x 4 o
  const int tg  = tid >> 3;   // 32 groups, t = tg + 32j
  const int l0  = 2 * T0 - 1;

  float acc[4][4];
#pragma unroll
  for (int i = 0; i < 4; i++)
#pragma unroll
    for (int j = 0; j < 4; j++) acc[i][j] = 0.f;

  for (int c0 = 0; c0 < 768; c0 += 16) {
    __syncthreads();
    for (int idx = tid; idx < 16 * 258; idx += 256) {
      int c = idx / 258, i = idx - c * 258;
      int l = l0 + i;
      float v = 0.f;
      if ((unsigned)l < 4096u) v = x[(b * 768 + c0 + c) * 4096 + l];
      xs[c * 260 + i] = v;
    }
    for (int idx = tid; idx < 2048; idx += 256) {
      int o = idx & 31, r = idx >> 5;           // r = c*4+k
      ws[r * 32 + o] = w[o * 3072 + c0 * 4 + r];
    }
    __syncthreads();
#pragma unroll 4
    for (int c = 0; c < 16; c++) {
      const float* wr = ws + c * 128 + og * 4;
      float4 w0 = *(const float4*)(wr);
      float4 w1 = *(const float4*)(wr + 32);
      float4 w2 = *(const float4*)(wr + 64);
      float4 w3 = *(const float4*)(wr + 96);
      const float* xr = xs + c * 260 + 2 * tg;
#pragma unroll
      for (int j = 0; j < 4; j++) {
        float2 xa = *(const float2*)(xr + 64 * j);
        float2 xb = *(const float2*)(xr + 64 * j + 2);
        acc[0][j] += w0.x * xa.x; acc[1][j] += w0.y * xa.x;
        acc[2][j] += w0.z * xa.x; acc[3][j] += w0.w * xa.x;
        acc[0][j] += w1.x * xa.y; acc[1][j] += w1.y * xa.y;
        acc[2][j] += w1.z * xa.y; acc[3][j] += w1.w * xa.y;
        acc[0][j] += w2.x * xb.x; acc[1][j] += w2.y * xb.x;
        acc[2][j] += w2.z * xb.x; acc[3][j] += w2.w * xb.x;
        acc[0][j] += w3.x * xb.y; acc[1][j] += w3.y * xb.y;
        acc[2][j] += w3.z * xb.y; acc[3][j] += w3.w * xb.y;
      }
    }
  }
#pragma unroll
  for (int i = 0; i < 4; i++) {
    int o = og * 4 + i;
    float bv = bias[o];
#pragma unroll
    for (int j = 0; j < 4; j++)
      out[(b * 32 + o) * 2048 + T0 + tg + 32 * j] = fmaxf(acc[i][j] + bv, 0.f);
  }
}

// =====================================================================
// conv2: (16,32,2048) -> (16,64,1024), k4 s2 p1, bias, ReLU
// grid (16,16).  tile 64o x 64t, c-chunks of 16.
// =====================================================================
__global__ void __launch_bounds__(256) k_conv2(
    const float* __restrict__ in, const float* __restrict__ w,
    const float* __restrict__ bias, float* __restrict__ out) {
  __shared__ float xs[16 * 132];   // 130 valid
  __shared__ float ws[64 * 64];
  const int b   = blockIdx.y;
  const int T0  = blockIdx.x * 64;
  const int tid = threadIdx.x;
  const int og  = tid & 15;
  const int tg  = tid >> 4;
  const int l0  = 2 * T0 - 1;

  float acc[4][4];
#pragma unroll
  for (int i = 0; i < 4; i++)
#pragma unroll
    for (int j = 0; j < 4; j++) acc[i][j] = 0.f;

  for (int c0 = 0; c0 < 32; c0 += 16) {
    __syncthreads();
    for (int idx = tid; idx < 16 * 130; idx += 256) {
      int c = idx / 130, i = idx - c * 130;
      int l = l0 + i;
      float v = 0.f;
      if ((unsigned)l < 2048u) v = in[(b * 32 + c0 + c) * 2048 + l];
      xs[c * 132 + i] = v;
    }
    for (int idx = tid; idx < 4096; idx += 256) {
      int o = idx & 63, r = idx >> 6;           // r = c*4+k
      ws[r * 64 + o] = w[o * 128 + c0 * 4 + r];
    }
    __syncthreads();
#pragma unroll 4
    for (int c = 0; c < 16; c++) {
      const float* wr = ws + c * 256 + og * 4;
      float4 w0 = *(const float4*)(wr);
      float4 w1 = *(const float4*)(wr + 64);
      float4 w2 = *(const float4*)(wr + 128);
      float4 w3 = *(const float4*)(wr + 192);
      const float* xr = xs + c * 132 + 2 * tg;
#pragma unroll
      for (int j = 0; j < 4; j++) {
        float2 xa = *(const float2*)(xr + 32 * j);
        float2 xb = *(const float2*)(xr + 32 * j + 2);
        acc[0][j] += w0.x * xa.x; acc[1][j] += w0.y * xa.x;
        acc[2][j] += w0.z * xa.x; acc[3][j] += w0.w * xa.x;
        acc[0][j] += w1.x * xa.y; acc[1][j] += w1.y * xa.y;
        acc[2][j] += w1.z * xa.y; acc[3][j] += w1.w * xa.y;
        acc[0][j] += w2.x * xb.x; acc[1][j] += w2.y * xb.x;
        acc[2][j] += w2.z * xb.x; acc[3][j] += w2.w * xb.x;
        acc[0][j] += w3.x * xb.y; acc[1][j] += w3.y * xb.y;
        acc[2][j] += w3.z * xb.y; acc[3][j] += w3.w * xb.y;
      }
    }
  }
#pragma unroll
  for (int i = 0; i < 4; i++) {
    int o = og * 4 + i;
    float bv = bias[o];
#pragma unroll
    for (int j = 0; j < 4; j++)
      out[(b * 64 + o) * 1024 + T0 + tg + 16 * j] = fmaxf(acc[i][j] + bv, 0.f);
  }
}

// =====================================================================
// conv3-type: (16,64,1024) -> (16,64,1024), k3 s1 p1, bias, NO relu
// (enc conv3 and dec conv1).  grid (16,16), c-chunks of 16.
// =====================================================================
__global__ void __launch_bounds__(256) k_conv3(
    const float* __restrict__ in, const float* __restrict__ w,
    const float* __restrict__ bias, float* __restrict__ out) {
  __shared__ float xs[16 * 68];    // 66 valid
  __shared__ float ws[48 * 64];    // [(c*3+k)][o]
  const int b   = blockIdx.y;
  const int T0  = blockIdx.x * 64;
  const int tid = threadIdx.x;
  const int og  = tid & 15;
  const int tg  = tid >> 4;

  float acc[4][4];
#pragma unroll
  for (int i = 0; i < 4; i++)
#pragma unroll
    for (int j = 0; j < 4; j++) acc[i][j] = 0.f;

  for (int c0 = 0; c0 < 64; c0 += 16) {
    __syncthreads();
    for (int idx = tid; idx < 16 * 66; idx += 256) {
      int c = idx / 66, i = idx - c * 66;
      int tt = T0 - 1 + i;
      float v = 0.f;
      if ((unsigned)tt < 1024u) v = in[(b * 64 + c0 + c) * 1024 + tt];
      xs[c * 68 + i] = v;
    }
    for (int idx = tid; idx < 3072; idx += 256) {
      int o = idx & 63, r = idx >> 6;           // r = c*3+k
      ws[r * 64 + o] = w[o * 192 + c0 * 3 + r];
    }
    __syncthreads();
#pragma unroll 4
    for (int c = 0; c < 16; c++) {
      const float* wr = ws + c * 192 + og * 4;
      float4 w0 = *(const float4*)(wr);
      float4 w1 = *(const float4*)(wr + 64);
      float4 w2 = *(const float4*)(wr + 128);
      const float* xr = xs + c * 68 + tg;
#pragma unroll
      for (int j = 0; j < 4; j++) {
        float x0 = xr[16 * j], x1 = xr[16 * j + 1], x2 = xr[16 * j + 2];
        acc[0][j] += w0.x * x0; acc[1][j] += w0.y * x0;
        acc[2][j] += w0.z * x0; acc[3][j] += w0.w * x0;
        acc[0][j] += w1.x * x1; acc[1][j] += w1.y * x1;
        acc[2][j] += w1.z * x1; acc[3][j] += w1.w * x1;
        acc[0][j] += w2.x * x2; acc[1][j] += w2.y * x2;
        acc[2][j] += w2.z * x2; acc[3][j] += w2.w * x2;
      }
    }
  }
#pragma unroll
  for (int i = 0; i < 4; i++) {
    int o = og * 4 + i;
    float bv = bias[o];
#pragma unroll
    for (int j = 0; j < 4; j++)
      out[(b * 64 + o) * 1024 + T0 + tg + 16 * j] = acc[i][j] + bv;
  }
}

// =====================================================================
// fused residual block: out = in + W2 @ relu(conv3(W1, relu(in)))
// w1 (32,64,3) no bias, w2 (64,32,1) no bias.  optional trailing relu.
// grid (16,16) block 256, tile 64t.
// =====================================================================
__global__ void __launch_bounds__(256) k_res(
    const float* __restrict__ in, const float* __restrict__ w1,
    const float* __restrict__ w2, float* __restrict__ out, int relu_out) {
  __shared__ float xs[32 * 68];    // relu(in) chunk, 66 valid
  __shared__ float w1s[96 * 32];   // [(c*3+k)][o]  (c<32 chunk)
  __shared__ float hs[32 * 65];    // h[32][64] padded
  __shared__ float w2s[32 * 64];   // [c][o]
  const int b   = blockIdx.y;
  const int T0  = blockIdx.x * 64;
  const int tid = threadIdx.x;
  // stage1 mapping: 32 o x 64 t
  const int og1 = tid & 7;
  const int tg1 = tid >> 3;        // 32 groups x 2 t (t = tg1 + 32j)
  // stage2 mapping: 64 o x 64 t
  const int og2 = tid & 15;
  const int tg2 = tid >> 4;        // 16 groups x 4 t

  // w2 into smem (used in stage2, protected by later syncs)
  for (int idx = tid; idx < 2048; idx += 256) {
    int o = idx & 63, c = idx >> 6;
    w2s[c * 64 + o] = w2[o * 32 + c];
  }

  float a1[4][2];
#pragma unroll
  for (int i = 0; i < 4; i++) { a1[i][0] = 0.f; a1[i][1] = 0.f; }

  for (int c0 = 0; c0 < 64; c0 += 32) {
    __syncthreads();
    for (int idx = tid; idx < 32 * 66; idx += 256) {
      int c = idx / 66, i = idx - c * 66;
      int tt = T0 - 1 + i;
      float v = 0.f;
      if ((unsigned)tt < 1024u) v = in[(b * 64 + c0 + c) * 1024 + tt];
      xs[c * 68 + i] = fmaxf(v, 0.f);
    }
    for (int idx = tid; idx < 3072; idx += 256) {
      int o = idx & 31, r = idx >> 5;           // r = c*3+k
      w1s[r * 32 + o] = w1[o * 192 + c0 * 3 + r];
    }
    __syncthreads();
#pragma unroll 4
    for (int c = 0; c < 32; c++) {
      const float* wr = w1s + c * 96 + og1 * 4;
      float4 w0 = *(const float4*)(wr);
      float4 wv1 = *(const float4*)(wr + 32);
      float4 wv2 = *(const float4*)(wr + 64);
      const float* xr = xs + c * 68 + tg1;
#pragma unroll
      for (int j = 0; j < 2; j++) {
        float x0 = xr[32 * j], x1 = xr[32 * j + 1], x2 = xr[32 * j + 2];
        a1[0][j] += w0.x * x0; a1[1][j] += w0.y * x0;
        a1[2][j] += w0.z * x0; a1[3][j] += w0.w * x0;
        a1[0][j] += wv1.x * x1; a1[1][j] += wv1.y * x1;
        a1[2][j] += wv1.z * x1; a1[3][j] += wv1.w * x1;
        a1[0][j] += wv2.x * x2; a1[1][j] += wv2.y * x2;
        a1[2][j] += wv2.z * x2; a1[3][j] += wv2.w * x2;
      }
    }
  }
  __syncthreads();
#pragma unroll
  for (int i = 0; i < 4; i++)
#pragma unroll
    for (int j = 0; j < 2; j++)
      hs[(og1 * 4 + i) * 65 + tg1 + 32 * j] = fmaxf(a1[i][j], 0.f);
  __syncthreads();

  float a2[4][4];
#pragma unroll
  for (int i = 0; i < 4; i++)
#pragma unroll
    for (int j = 0; j < 4; j++) a2[i][j] = 0.f;
#pragma unroll 4
  for (int c = 0; c < 32; c++) {
    float4 wv = *(const float4*)(w2s + c * 64 + og2 * 4);
    const float* hr = hs + c * 65 + tg2;
#pragma unroll
    for (int j = 0; j < 4; j++) {
      float h = hr[16 * j];
      a2[0][j] += wv.x * h; a2[1][j] += wv.y * h;
      a2[2][j] += wv.z * h; a2[3][j] += wv.w * h;
    }
  }
#pragma unroll
  for (int i = 0; i < 4; i++) {
    int o = og2 * 4 + i;
#pragma unroll
    for (int j = 0; j < 4; j++) {
      int t = T0 + tg2 + 16 * j;
      float r = in[(b * 64 + o) * 1024 + t] + a2[i][j];
      if (relu_out) r = fmaxf(r, 0.f);
      out[(b * 64 + o) * 1024 + t] = r;
    }
  }
}

// =====================================================================
// prevq: 1x1 conv 64->64 + bias.  grid (16,16)
// =====================================================================
__global__ void __launch_bounds__(256) k_prevq(
    const float* __restrict__ in, const float* __restrict__ w,
    const float* __restrict__ bias, float* __restrict__ out) {
  __shared__ float ins[64 * 66];
  __shared__ float ws[64 * 64];    // [c][o]
  const int b   = blockIdx.y;
  const int T0  = blockIdx.x * 64;
  const int tid = threadIdx.x;
  const int og  = tid & 15;
  const int tg  = tid >> 4;

  for (int idx = tid; idx < 4096; idx += 256) {
    int c = idx >> 6, t = idx & 63;
    ins[c * 66 + t] = in[(b * 64 + c) * 1024 + T0 + t];
  }
  for (int idx = tid; idx < 4096; idx += 256) {
    int o = idx & 63, c = idx >> 6;
    ws[c * 64 + o] = w[o * 64 + c];
  }
  __syncthreads();

  float acc[4][4];
#pragma unroll
  for (int i = 0; i < 4; i++)
#pragma unroll
    for (int j = 0; j < 4; j++) acc[i][j] = 0.f;
#pragma unroll 4
  for (int c = 0; c < 64; c++) {
    float4 wv = *(const float4*)(ws + c * 64 + og * 4);
    const float* xr = ins + c * 66 + tg;
#pragma unroll
    for (int j = 0; j < 4; j++) {
      float x = xr[16 * j];
      acc[0][j] += wv.x * x; acc[1][j] += wv.y * x;
      acc[2][j] += wv.z * x; acc[3][j] += wv.w * x;
    }
  }
#pragma unroll
  for (int i = 0; i < 4; i++) {
    int o = og * 4 + i;
    float bv = bias[o];
#pragma unroll
    for (int j = 0; j < 4; j++)
      out[(b * 64 + o) * 1024 + T0 + tg + 16 * j] = acc[i][j] + bv;
  }
}

// =====================================================================
// VQ: e2 precompute + per-token argmin + straight-through write
// =====================================================================
__global__ void k_e2(const float* __restrict__ emb) {
  int i = threadIdx.x;              // 512 threads
  float s = 0.f;
#pragma unroll 8
  for (int c = 0; c < 64; c++) {
    float e = emb[i * 64 + c];
    s += e * e;
  }
  g_e2[i] = s;
}

__global__ void __launch_bounds__(128) k_vq(
    const float* __restrict__ z, const float* __restrict__ emb,
    float* __restrict__ q) {
  __shared__ float es[64 * 64];     // 64-code chunk
  __shared__ float e2s[64];
  const int tid   = threadIdx.x;
  const int token = blockIdx.x * 128 + tid;
  const int b = token >> 10;
  const int t = token & 1023;

  float zr[64];
#pragma unroll
  for (int c = 0; c < 64; c++) zr[c] = z[(b * 64 + c) * 1024 + t];

  float bs = 3.4e38f;
  int bi = 0;
  for (int cb = 0; cb < 512; cb += 64) {
    __syncthreads();
    for (int idx = tid; idx < 4096; idx += 128) es[idx] = emb[cb * 64 + idx];
    if (tid < 64) e2s[tid] = g_e2[cb + tid];
    __syncthreads();
#pragma unroll 2
    for (int code = 0; code < 64; code++) {
      float dot = 0.f;
      const float4* er = (const float4*)(es + code * 64);
#pragma unroll
      for (int cq = 0; cq < 16; cq++) {
        float4 e4 = er[cq];
        dot += zr[4 * cq] * e4.x + zr[4 * cq + 1] * e4.y
             + zr[4 * cq + 2] * e4.z + zr[4 * cq + 3] * e4.w;
      }
      float score = e2s[code] - 2.f * dot;
      if (score < bs) { bs = score; bi = cb + code; }
    }
  }
  // straight-through: q = z + (e - z), same op order as reference
  const float* eb = emb + bi * 64;
#pragma unroll 8
  for (int c = 0; c < 64; c++) {
    float zv = zr[c];
    q[(b * 64 + c) * 1024 + t] = zv + (eb[c] - zv);
  }
}

// =====================================================================
// dect1: ConvTranspose 64->32 k4 s2 p1 + bias + ReLU
// (16,64,1024) -> (16,32,2048).  grid (16,16), tile 64 s -> 128 t.
// t=2s:   w[·,·,1]*x[s]   + w[·,·,3]*x[s-1]
// t=2s+1: w[·,·,0]*x[s+1] + w[·,·,2]*x[s]
// =====================================================================
__global__ void __launch_bounds__(256) k_dect1(
    const float* __restrict__ in, const float* __restrict__ w,
    const float* __restrict__ bias, float* __restrict__ out) {
  __shared__ float xs[32 * 68];    // 66 valid: x[S0-1 .. S0+64]
  __shared__ float ws[128 * 32];   // [(c*4+k)][o]
  const int b   = blockIdx.y;
  const int S0  = blockIdx.x * 64;
  const int tid = threadIdx.x;
  const int og  = tid & 7;         // 8 x 4 o = 32
  const int sg  = tid >> 3;        // 32 groups x 2 s

  float ae[4][2], ao[4][2];
#pragma unroll
  for (int i = 0; i < 4; i++)
#pragma unroll
    for (int j = 0; j < 2; j++) { ae[i][j] = 0.f; ao[i][j] = 0.f; }

  for (int c0 = 0; c0 < 64; c0 += 32) {
    __syncthreads();
    for (int idx = tid; idx < 32 * 66; idx += 256) {
      int c = idx / 66, i = idx - c * 66;
      int ss = S0 - 1 + i;
      float v = 0.f;
      if ((unsigned)ss < 1024u) v = in[(b * 64 + c0 + c) * 1024 + ss];
      xs[c * 68 + i] = v;
    }
    for (int idx = tid; idx < 4096; idx += 256) {
      int o = idx & 31, r = idx >> 5;           // r = c*4+k
      ws[r * 32 + o] = w[(c0 + (r >> 2)) * 128 + o * 4 + (r & 3)];
    }
    __syncthreads();
#pragma unroll 4
    for (int c = 0; c < 32; c++) {
      const float* wr = ws + c * 128 + og * 4;
      float4 w0 = *(const float4*)(wr);
      float4 w1 = *(const float4*)(wr + 32);
      float4 w2 = *(const float4*)(wr + 64);
      float4 w3 = *(const float4*)(wr + 96);
      const float* xr = xs + c * 68 + sg;
#pragma unroll
      for (int j = 0; j < 2; j++) {
        float xm = xr[32 * j];          // x[s-1]
        float xc = xr[32 * j + 1];      // x[s]
        float xp = xr[32 * j + 2];      // x[s+1]
        ae[0][j] += w1.x * xc + w3.x * xm;
        ae[1][j] += w1.y * xc + w3.y * xm;
        ae[2][j] += w1.z * xc + w3.z * xm;
        ae[3][j] += w1.w * xc + w3.w * xm;
        ao[0][j] += w0.x * xp + w2.x * xc;
        ao[1][j] += w0.y * xp + w2.y * xc;
        ao[2][j] += w0.z * xp + w2.z * xc;
        ao[3][j] += w0.w * xp + w2.w * xc;
      }
    }
  }
#pragma unroll
  for (int i = 0; i < 4; i++) {
    int o = og * 4 + i;
    float bv = bias[o];
#pragma unroll
    for (int j = 0; j < 2; j++) {
      int te = 2 * (S0 + sg + 32 * j);
      out[(b * 32 + o) * 2048 + te]     = fmaxf(ae[i][j] + bv, 0.f);
      out[(b * 32 + o) * 2048 + te + 1] = fmaxf(ao[i][j] + bv, 0.f);
    }
  }
}

// =====================================================================
// dect2: ConvTranspose 32->64 k4 s2 p1 + bias (final output)
// (16,32,2048) -> (16,64,4096).  grid (32,16), tile 64 s -> 128 t.
// =====================================================================
__global__ void __launch_bounds__(256) k_dect2(
    const float* __restrict__ in, const float* __restrict__ w,
    const float* __restrict__ bias, float* __restrict__ out) {
  __shared__ float xs[32 * 68];
  __shared__ float ws[128 * 64];   // [(c*4+k)][o]
  const int b   = blockIdx.y;
  const int S0  = blockIdx.x * 64;
  const int tid = threadIdx.x;
  const int og  = tid & 15;        // 16 x 4 o = 64
  const int sg  = tid >> 4;        // 16 groups x 4 s

  for (int idx = tid; idx < 32 * 66; idx += 256) {
    int c = idx / 66, i = idx - c * 66;
    int ss = S0 - 1 + i;
    float v = 0.f;
    if ((unsigned)ss < 2048u) v = in[(b * 32 + c) * 2048 + ss];
    xs[c * 68 + i] = v;
  }
  for (int idx = tid; idx < 8192; idx += 256) {
    int o = idx & 63, r = idx >> 6;             // r = c*4+k
    ws[r * 64 + o] = w[(r >> 2) * 256 + o * 4 + (r & 3)];
  }
  __syncthreads();

  float ae[4][4], ao[4][4];
#pragma unroll
  for (int i = 0; i < 4; i++)
#pragma unroll
    for (int j = 0; j < 4; j++) { ae[i][j] = 0.f; ao[i][j] = 0.f; }

#pragma unroll 2
  for (int c = 0; c < 32; c++) {
    const float* wr = ws + c * 256 + og * 4;
    float4 w0 = *(const float4*)(wr);
    float4 w1 = *(const float4*)(wr + 64);
    float4 w2 = *(const float4*)(wr + 128);
    float4 w3 = *(const float4*)(wr + 192);
    const float* xr = xs + c * 68 + sg;
#pragma unroll
    for (int j = 0; j < 4; j++) {
      float xm = xr[16 * j];
      float xc = xr[16 * j + 1];
      float xp = xr[16 * j + 2];
      ae[0][j] += w1.x * xc + w3.x * xm;
      ae[1][j] += w1.y * xc + w3.y * xm;
      ae[2][j] += w1.z * xc + w3.z * xm;
      ae[3][j] += w1.w * xc + w3.w * xm;
      ao[0][j] += w0.x * xp + w2.x * xc;
      ao[1][j] += w0.y * xp + w2.y * xc;
      ao[2][j] += w0.z * xp + w2.z * xc;
      ao[3][j] += w0.w * xp + w2.w * xc;
    }
  }
#pragma unroll
  for (int i = 0; i < 4; i++) {
    int o = og * 4 + i;
    float bv = bias[o];
#pragma unroll
    for (int j = 0; j < 4; j++) {
      int te = 2 * (S0 + sg + 16 * j);
      out[(b * 64 + o) * 4096 + te]     = ae[i][j] + bv;
      out[(b * 64 + o) * 4096 + te + 1] = ao[i][j] + bv;
    }
  }
}

// =====================================================================
extern "C" void kernel_launch(void* const* d_in, const int* in_sizes, int n_in,
                              void* d_out, int out_size) {
  const float* x        = (const float*)d_in[0];
  const float* enc_w1   = (const float*)d_in[1];
  const float* enc_b1   = (const float*)d_in[2];
  const float* enc_w2   = (const float*)d_in[3];
  const float* enc_b2   = (const float*)d_in[4];
  const float* enc_w3   = (const float*)d_in[5];
  const float* enc_b3   = (const float*)d_in[6];
  const float* enc_r0w1 = (const float*)d_in[7];
  const float* enc_r0w2 = (const float*)d_in[8];
  const float* enc_r1w1 = (const float*)d_in[9];
  const float* enc_r1w2 = (const float*)d_in[10];
  const float* prevq_w  = (const float*)d_in[11];
  const float* prevq_b  = (const float*)d_in[12];
  const float* emb      = (const float*)d_in[13];
  const float* dec_w1   = (const float*)d_in[14];
  const float* dec_b1   = (const float*)d_in[15];
  const float* dec_r0w1 = (const float*)d_in[16];
  const float* dec_r0w2 = (const float*)d_in[17];
  const float* dec_r1w1 = (const float*)d_in[18];
  const float* dec_r1w2 = (const float*)d_in[19];
  const float* dect1_w  = (const float*)d_in[20];
  const float* dect1_b  = (const float*)d_in[21];
  const float* dect2_w  = (const float*)d_in[22];
  const float* dect2_b  = (const float*)d_in[23];
  float* out = (float*)d_out;

  float *A, *B;
  cudaGetSymbolAddress((void**)&A, g_bufA);
  cudaGetSymbolAddress((void**)&B, g_bufB);

  dim3 blk(256);
  k_e2<<<1, 512>>>(emb);
  k_conv1<<<dim3(16, BATCH), blk>>>(x, enc_w1, enc_b1, A);
  k_conv2<<<dim3(16, BATCH), blk>>>(A, enc_w2, enc_b2, B);
  k_conv3<<<dim3(16, BATCH), blk>>>(B, enc_w3, enc_b3, A);
  k_res  <<<dim3(16, BATCH), blk>>>(A, enc_r0w1, enc_r0w2, B, 0);
  k_res  <<<dim3(16, BATCH), blk>>>(B, enc_r1w1, enc_r1w2, A, 1);
  k_prevq<<<dim3(16, BATCH), blk>>>(A, prevq_w, prevq_b, B);   // z in B
  k_vq   <<<128, 128>>>(B, emb, A);                            // q in A
  k_conv3<<<dim3(16, BATCH), blk>>>(A, dec_w1, dec_b1, B);
  k_res  <<<dim3(16, BATCH), blk>>>(B, dec_r0w1, dec_r0w2, A, 0);
  k_res  <<<dim3(16, BATCH), blk>>>(A, dec_r1w1, dec_r1w2, B, 1);
  k_dect1<<<dim3(16, BATCH), blk>>>(B, dect1_w, dect1_b, A);
  k_dect2<<<dim3(32, BATCH), blk>>>(A, dect2_w, dect2_b, out);
  (void)in_sizes; (void)n_in; (void)out_size;
}